// round 14
// baseline (speedup 1.0000x reference)
#include <cuda_runtime.h>
#include <cuda_fp16.h>
#include <math.h>
#include <stdint.h>

#define NB 4
#define NL 4096
#define NC 1024
#define NH 8
#define NR 512
#define ND 64
#define LAMBDA_INIT 0.8f
#define EPS 1e-6f

#define SZQ   (NB*NH*NR*ND)

// ======================= device scratch (no allocs allowed) ==================
__device__ __half g_xd [NB*NR*NC];
__device__ __half g_W  [3*NC*NC];          // Wq,Wk,Wv
__device__ __half g_Wo [NC*NC];
__device__ __half g_q12[2*SZQ];
__device__ __half g_k12[2*SZQ];
__device__ __half g_vt [NB*NH*128*NR];
__device__ float  g_o  [2*NB*NH*NR*128];   // O1 | O2 (fp32)
__device__ __half g_y  [NB*NR*NC];
__device__ float  g_lam[1];

// ======================= asm helpers =========================================
__device__ __forceinline__ uint32_t smem_u32(const void* p){
    uint32_t a;
    asm("{ .reg .u64 t; cvta.to.shared.u64 t, %1; cvt.u32.u64 %0, t; }" : "=r"(a) : "l"(p));
    return a;
}
__device__ __forceinline__ void cpa16(uint32_t d, const void* s){
    asm volatile("cp.async.cg.shared.global [%0], [%1], 16;" :: "r"(d), "l"(s));
}
#define CP_COMMIT() asm volatile("cp.async.commit_group;" ::: "memory")
#define CP_WAIT0()  asm volatile("cp.async.wait_group 0;" ::: "memory")
#define CP_WAIT1()  asm volatile("cp.async.wait_group 1;" ::: "memory")

__device__ __forceinline__ void mma16816(float* c,
    uint32_t a0, uint32_t a1, uint32_t a2, uint32_t a3, uint32_t b0, uint32_t b1)
{
    asm volatile(
        "mma.sync.aligned.m16n8k16.row.col.f32.f16.f16.f32 "
        "{%0,%1,%2,%3}, {%4,%5,%6,%7}, {%8,%9}, {%0,%1,%2,%3};"
        : "+f"(c[0]), "+f"(c[1]), "+f"(c[2]), "+f"(c[3])
        : "r"(a0), "r"(a1), "r"(a2), "r"(a3), "r"(b0), "r"(b1));
}
#define LDSM4(r0,r1,r2,r3, addr) \
    asm volatile("ldmatrix.sync.aligned.m8n8.x4.shared.b16 {%0,%1,%2,%3}, [%4];" \
        : "=r"(r0),"=r"(r1),"=r"(r2),"=r"(r3) : "r"(addr))

__device__ __forceinline__ unsigned short h1(float v){
    return __half_as_ushort(__float2half_rn(v));
}
__device__ __forceinline__ uint32_t pk2(float a, float b){
    __half2 h = __floats2half2_rn(a, b);
    return *(uint32_t*)&h;
}

// ======================= HMMA fp16 batched NT GEMM (R10 config) ==============
#define ROW_B   144
#define TILE_B  (128*ROW_B)          // 18432
#define STG_B   (2*TILE_B)           // 36864
#define GEMM_SMEM (3*STG_B)          // 110592

__device__ __forceinline__ void ld_stage(uint32_t sbase, int tid, long long c64,
    const __half* Ab, const __half* Bb, int K)
{
    int seg = tid & 7;
    #pragma unroll
    for (int it = 0; it < 8; it++) {
        int i = tid + it*256;
        int r = (i >> 3) & 127;
        const __half* src = (it < 4) ? Ab : Bb;
        cpa16(sbase + (it >> 2)*TILE_B + r*ROW_B + seg*16,
              src + (long long)r*K + c64 + seg*8);
    }
    CP_COMMIT();
}

__global__ __launch_bounds__(256, 2)
void gemm_mma(const __half* __restrict__ A, const __half* __restrict__ B,
              float* __restrict__ C, int M, int N, int K,
              long long sA, long long sB, long long sC, float alpha, int mode,
              const float* __restrict__ w1, const float* __restrict__ w2)
{
    extern __shared__ char sm[];
    uint32_t sb = smem_u32(sm);
    const int tid  = threadIdx.x;
    const int wid  = tid >> 5, lane = tid & 31;
    const int gid  = lane >> 2, tig = lane & 3;
    const int wm   = (wid & 1) * 64;
    const int wn   = (wid >> 1) * 32;
    const int bm   = blockIdx.y * 128, bn = blockIdx.x * 128;
    const int z    = blockIdx.z;

    const __half* Ab = A + z*sA + (long long)bm*K;
    const __half* Bb = B + z*sB + (long long)bn*K;

    const int a_row = (lane & 7) + ((lane & 8)  ? 8 : 0);
    const int a_col = (lane & 16) ? 16 : 0;
    const int b_row = (lane & 7) + ((lane & 16) ? 8 : 0);
    const int b_col = (lane & 8)  ? 16 : 0;

    float acc[4][4][4];
    #pragma unroll
    for (int mi = 0; mi < 4; mi++)
        #pragma unroll
        for (int ni = 0; ni < 4; ni++)
            #pragma unroll
            for (int t = 0; t < 4; t++) acc[mi][ni][t] = 0.f;

    const int nch = K >> 6;
    ld_stage(sb, tid, 0, Ab, Bb, K);
    if (nch > 1) ld_stage(sb + STG_B, tid, 64, Ab, Bb, K);

    for (int c = 0; c < nch; c++) {
        if (c + 1 < nch) CP_WAIT1(); else CP_WAIT0();
        __syncthreads();
        if (c + 2 < nch)
            ld_stage(sb + ((c + 2) % 3)*STG_B, tid, (long long)(c + 2)*64, Ab, Bb, K);

        const uint32_t p  = sb + (c % 3)*STG_B;
        const uint32_t pA = p, pB = p + TILE_B;

        #pragma unroll
        for (int kk = 0; kk < 4; kk++) {
            const int ko = kk*32;
            uint32_t bh[4][2];
            #pragma unroll
            for (int nj = 0; nj < 2; nj++) {
                uint32_t bd = pB + (wn + nj*16 + b_row)*ROW_B + ko + b_col;
                LDSM4(bh[2*nj][0], bh[2*nj][1], bh[2*nj+1][0], bh[2*nj+1][1], bd);
            }
            #pragma unroll
            for (int mi = 0; mi < 4; mi++) {
                uint32_t ah[4];
                uint32_t ad = pA + (wm + mi*16 + a_row)*ROW_B + ko + a_col;
                LDSM4(ah[0], ah[1], ah[2], ah[3], ad);
                #pragma unroll
                for (int ni = 0; ni < 4; ni++)
                    mma16816(acc[mi][ni], ah[0], ah[1], ah[2], ah[3],
                             bh[ni][0], bh[ni][1]);
            }
        }
    }

    if (mode == 0 || mode == 1) {
        float* Cb = C + z*sC;
        #pragma unroll
        for (int mi = 0; mi < 4; mi++) {
            #pragma unroll
            for (int ni = 0; ni < 4; ni++) {
                int row = bm + wm + mi*16 + gid;
                int col = bn + wn + ni*8 + tig*2;
                float v0 = acc[mi][ni][0]*alpha, v1 = acc[mi][ni][1]*alpha;
                float v2 = acc[mi][ni][2]*alpha, v3 = acc[mi][ni][3]*alpha;
                if (mode == 1) {
                    v0 /= (1.f + __expf(-v0)); v1 /= (1.f + __expf(-v1));
                    v2 /= (1.f + __expf(-v2)); v3 /= (1.f + __expf(-v3));
                }
                *(float2*)&Cb[(long long)row*N + col]       = make_float2(v0, v1);
                *(float2*)&Cb[(long long)(row + 8)*N + col] = make_float2(v2, v3);
            }
        }
        return;
    }

    // ---------- mode 3: fused QKV epilogue (stage to smem first) --------------
    __syncthreads();
    float* esm = (float*)sm;                    // 128 x 132 floats
    const bool vtr = (z == 2);
    #pragma unroll
    for (int mi = 0; mi < 4; mi++) {
        #pragma unroll
        for (int ni = 0; ni < 4; ni++) {
            int r0 = wm + mi*16 + gid;
            int cc = wn + ni*8 + tig*2;
            if (vtr) {
                esm[cc*132 + r0]         = acc[mi][ni][0];
                esm[(cc+1)*132 + r0]     = acc[mi][ni][1];
                esm[cc*132 + r0 + 8]     = acc[mi][ni][2];
                esm[(cc+1)*132 + r0 + 8] = acc[mi][ni][3];
            } else {
                esm[r0*132 + cc]         = acc[mi][ni][0];
                esm[r0*132 + cc + 1]     = acc[mi][ni][1];
                esm[(r0+8)*132 + cc]     = acc[mi][ni][2];
                esm[(r0+8)*132 + cc + 1] = acc[mi][ni][3];
            }
        }
    }
    __syncthreads();

    const int h = blockIdx.x;              // tile cols = one head
    if (z < 2) {
        const float* w = z ? w2 : w1;
        const int gidx = lane & 15, sgi = lane >> 4;
        const int dmb = (gidx & 7) * 4;
        float4 wv = ((const float4*)w)[gidx];
        float sn[4], cs[4];
        #pragma unroll
        for (int j = 0; j < 4; j++) {
            float f = exp2f(-0.41524101186351494f * (float)(dmb + j));
            __sincosf((float)h * f, &sn[j], &cs[j]);
        }
        __half* dh = (z == 0 ? g_q12 : g_k12) + (long long)sgi*SZQ;
        const bool lo = (gidx & 8) == 0;
        for (int r = wid; r < 128; r += 8) {
            float4 xv = *(float4*)&esm[r*132 + sgi*64 + gidx*4];
            float ssq = xv.x*xv.x + xv.y*xv.y + xv.z*xv.z + xv.w*xv.w;
            #pragma unroll
            for (int o = 8; o; o >>= 1) ssq += __shfl_xor_sync(0xffffffffu, ssq, o);
            float inv = rsqrtf(ssq*(1.f/64.f) + EPS);
            float n0 = xv.x*inv*wv.x, n1 = xv.y*inv*wv.y;
            float n2 = xv.z*inv*wv.z, n3 = xv.w*inv*wv.w;
            float p0 = __shfl_xor_sync(0xffffffffu, n0, 8);
            float p1 = __shfl_xor_sync(0xffffffffu, n1, 8);
            float p2 = __shfl_xor_sync(0xffffffffu, n2, 8);
            float p3 = __shfl_xor_sync(0xffffffffu, n3, 8);
            ushort4 hh;
            hh.x = h1(lo ? n0*cs[0] - p0*sn[0] : p0*sn[0] + n0*cs[0]);
            hh.y = h1(lo ? n1*cs[1] - p1*sn[1] : p1*sn[1] + n1*cs[1]);
            hh.z = h1(lo ? n2*cs[2] - p2*sn[2] : p2*sn[2] + n2*cs[2]);
            hh.w = h1(lo ? n3*cs[3] - p3*sn[3] : p3*sn[3] + n3*cs[3]);
            int tok = bm + r, b = tok >> 9, il = tok & 511;
            long long off = ((long long)((b*NH + h)*NR) + il)*64 + gidx*4;
            *(ushort4*)(dh + off) = hh;
        }
    } else {
        const int b = bm >> 9, ibase = bm & 511;
        const int bh2 = b*NH + h;
        #pragma unroll
        for (int it = 0; it < 32; it++) {
            int e = tid + it*256;
            int cix = e >> 6, ip = e & 63, i = ip*2;
            float2 vv = *(float2*)&esm[cix*132 + i];
            long long o = ((long long)(bh2*128 + cix))*NR + ibase + i;
            *(ushort2*)(g_vt + o) = make_ushort2(h1(vv.x), h1(vv.y));
        }
    }
}

// ======================= fused flash attention (512 thr, key-split) ==========
// grid: (1, 4 q-blocks, 64)  z = s*32 + bh.  16 warps = 8 row-groups x 2 key-halves.
// Each warp: 16 rows x 64-key half per chunk, independent online softmax,
// k-partial O over all 128 cols; halves merged once at the end via smem.
#define FQ_ROW 144
#define FV_ROW 272
#define FK_B   (128*FQ_ROW)      // 18432
#define FV_B   (128*FV_ROW)      // 34816
#define FSTG   (FK_B + FV_B)     // 53248
#define FLASH_SMEM (FK_B + 2*FSTG)  // 124928
#define MO_ROW 132               // merge buffer row stride (floats)
#define MO_B   (128*MO_ROW*4)    // 67584 bytes

__device__ __forceinline__ void flash_ld(uint32_t dst, int tid, int j,
    const __half* Kg, const __half* Vg)
{
    #pragma unroll
    for (int t = 0; t < 2; t++) {                    // K-chunk: 128 x 64
        int i = tid + t*512;
        int r = i >> 3, seg = i & 7;
        cpa16(dst + r*FQ_ROW + seg*16, Kg + (long long)(j*128 + r)*64 + seg*8);
    }
    #pragma unroll
    for (int t = 0; t < 4; t++) {                    // V-chunk: 128c x 128i
        int i = tid + t*512;
        int c = i >> 4, sg = i & 15;
        cpa16(dst + FK_B + c*FV_ROW + sg*16, Vg + (long long)c*NR + j*128 + sg*8);
    }
    CP_COMMIT();
}

__global__ __launch_bounds__(512, 1)
void flash_attn(const __half* __restrict__ q12, const __half* __restrict__ k12,
                const __half* __restrict__ vt, float* __restrict__ O)
{
    extern __shared__ char sm[];
    uint32_t sb = smem_u32(sm);
    const uint32_t sQ = sb;
    const int tid = threadIdx.x, wid = tid >> 5, lane = tid & 31;
    const int gid = lane >> 2, tig = lane & 3;
    const int rg = wid >> 1, kh = wid & 1;       // row-group, key-half
    const int wq = rg * 16;
    const int z = blockIdx.z, s = z >> 5, bh = z & 31;
    const int qblk = blockIdx.y;

    const __half* Qg = q12 + (long long)s*SZQ + ((long long)(bh*NR) + qblk*128)*64;
    const __half* Kg = k12 + (long long)s*SZQ + (long long)(bh*NR)*64;
    const __half* Vg = vt  + (long long)bh*128*NR;

    // load Q (grouped with chunk 0)
    #pragma unroll
    for (int t = 0; t < 2; t++) {
        int i = tid + t*512;
        int r = i >> 3, seg = i & 7;
        cpa16(sQ + r*FQ_ROW + seg*16, Qg + (long long)r*64 + seg*8);
    }
    flash_ld(sQ + FK_B, tid, 0, Kg, Vg);

    const int a_row = (lane & 7) + ((lane & 8)  ? 8 : 0);
    const int a_col = (lane & 16) ? 16 : 0;
    const int b_row = (lane & 7) + ((lane & 16) ? 8 : 0);
    const int b_col = (lane & 8)  ? 16 : 0;

    float acc_o[16][4];
    #pragma unroll
    for (int ni = 0; ni < 16; ni++)
        #pragma unroll
        for (int t = 0; t < 4; t++) acc_o[ni][t] = 0.f;
    float m0 = -1e30f, m1 = -1e30f, l0 = 0.f, l1 = 0.f;

    for (int j = 0; j < 4; j++) {
        __syncthreads();
        if (j + 1 < 4)
            flash_ld(sQ + FK_B + ((j + 1) & 1)*FSTG, tid, j + 1, Kg, Vg);
        if (j + 1 < 4) CP_WAIT1(); else CP_WAIT0();
        __syncthreads();

        const uint32_t pK = sQ + FK_B + (j & 1)*FSTG;
        const uint32_t pV = pK + FK_B;

        // ---- S = 0.125 * Q K^T  (16 rows x 64 keys of this half) ----
        float sc[8][4];
        #pragma unroll
        for (int ni = 0; ni < 8; ni++)
            #pragma unroll
            for (int t = 0; t < 4; t++) sc[ni][t] = 0.f;
        #pragma unroll
        for (int kd = 0; kd < 4; kd++) {
            uint32_t ah[4];
            uint32_t ad = sQ + (wq + a_row)*FQ_ROW + kd*32 + a_col;
            LDSM4(ah[0], ah[1], ah[2], ah[3], ad);
            #pragma unroll
            for (int nj = 0; nj < 4; nj++) {
                uint32_t b0, b1, b2, b3;
                uint32_t bd = pK + (kh*64 + nj*16 + b_row)*FQ_ROW + kd*32 + b_col;
                LDSM4(b0, b1, b2, b3, bd);
                mma16816(sc[2*nj],   ah[0], ah[1], ah[2], ah[3], b0, b1);
                mma16816(sc[2*nj+1], ah[0], ah[1], ah[2], ah[3], b2, b3);
            }
        }
        #pragma unroll
        for (int ni = 0; ni < 8; ni++)
            #pragma unroll
            for (int t = 0; t < 4; t++) sc[ni][t] *= 0.125f;

        // ---- online softmax over this half's 64 keys ----
        float cm0 = -1e30f, cm1 = -1e30f;
        #pragma unroll
        for (int ni = 0; ni < 8; ni++) {
            cm0 = fmaxf(cm0, fmaxf(sc[ni][0], sc[ni][1]));
            cm1 = fmaxf(cm1, fmaxf(sc[ni][2], sc[ni][3]));
        }
        cm0 = fmaxf(cm0, __shfl_xor_sync(0xffffffffu, cm0, 1));
        cm0 = fmaxf(cm0, __shfl_xor_sync(0xffffffffu, cm0, 2));
        cm1 = fmaxf(cm1, __shfl_xor_sync(0xffffffffu, cm1, 1));
        cm1 = fmaxf(cm1, __shfl_xor_sync(0xffffffffu, cm1, 2));
        float nm0 = fmaxf(m0, cm0), nm1 = fmaxf(m1, cm1);
        float f0 = __expf(m0 - nm0), f1 = __expf(m1 - nm1);
        m0 = nm0; m1 = nm1;

        uint32_t ph[4][4];
        float s0 = 0.f, s1 = 0.f;
        #pragma unroll
        for (int t = 0; t < 4; t++) {
            float e00 = __expf(sc[2*t][0]  - nm0), e01 = __expf(sc[2*t][1]  - nm0);
            float e02 = __expf(sc[2*t][2]  - nm1), e03 = __expf(sc[2*t][3]  - nm1);
            float e10 = __expf(sc[2*t+1][0]- nm0), e11 = __expf(sc[2*t+1][1]- nm0);
            float e12 = __expf(sc[2*t+1][2]- nm1), e13 = __expf(sc[2*t+1][3]- nm1);
            s0 += e00 + e01 + e10 + e11;
            s1 += e02 + e03 + e12 + e13;
            ph[t][0] = pk2(e00, e01);
            ph[t][1] = pk2(e02, e03);
            ph[t][2] = pk2(e10, e11);
            ph[t][3] = pk2(e12, e13);
        }
        s0 += __shfl_xor_sync(0xffffffffu, s0, 1);
        s0 += __shfl_xor_sync(0xffffffffu, s0, 2);
        s1 += __shfl_xor_sync(0xffffffffu, s1, 1);
        s1 += __shfl_xor_sync(0xffffffffu, s1, 2);
        l0 = l0*f0 + s0;
        l1 = l1*f1 + s1;

        #pragma unroll
        for (int ni = 0; ni < 16; ni++) {
            acc_o[ni][0] *= f0; acc_o[ni][1] *= f0;
            acc_o[ni][2] *= f1; acc_o[ni][3] *= f1;
        }

        // ---- O += P V  (k = this half's 64 keys, n = 128 cols) ----
        #pragma unroll
        for (int t = 0; t < 4; t++) {
            #pragma unroll
            for (int nj = 0; nj < 8; nj++) {
                uint32_t b0, b1, b2, b3;
                uint32_t bd = pV + (nj*16 + b_row)*FV_ROW + (kh*64 + t*16)*2 + b_col;
                LDSM4(b0, b1, b2, b3, bd);
                mma16816(acc_o[2*nj],   ph[t][0], ph[t][1], ph[t][2], ph[t][3], b0, b1);
                mma16816(acc_o[2*nj+1], ph[t][0], ph[t][1], ph[t][2], ph[t][3], b2, b3);
            }
        }
    }

    // ---- merge the two key-halves via smem, then write O --------------------
    __syncthreads();                              // all mainloop smem reads done
    float* msm   = (float*)sm;                    // 128 x 132 floats
    float* mst_m = (float*)(sm + MO_B);           // 128 m values
    float* mst_l = mst_m + 128;                   // 128 l values

    if (kh == 1) {
        #pragma unroll
        for (int ni = 0; ni < 16; ni++) {
            int col = ni*8 + tig*2;
            int r0 = wq + gid;
            msm[r0*MO_ROW + col]       = acc_o[ni][0];
            msm[r0*MO_ROW + col + 1]   = acc_o[ni][1];
            msm[(r0+8)*MO_ROW + col]     = acc_o[ni][2];
            msm[(r0+8)*MO_ROW + col + 1] = acc_o[ni][3];
        }
        if (tig == 0) {
            mst_m[wq + gid]     = m0;  mst_l[wq + gid]     = l0;
            mst_m[wq + gid + 8] = m1;  mst_l[wq + gid + 8] = l1;
        }
    }
    __syncthreads();

    if (kh == 0) {
        int r0 = wq + gid, r1 = r0 + 8;
        float mb0 = mst_m[r0], lb0 = mst_l[r0];
        float mb1 = mst_m[r1], lb1 = mst_l[r1];
        float M0 = fmaxf(m0, mb0), M1 = fmaxf(m1, mb1);
        float fa0 = __expf(m0 - M0), fb0 = __expf(mb0 - M0);
        float fa1 = __expf(m1 - M1), fb1 = __expf(mb1 - M1);
        float i0 = 1.f / (fa0*l0 + fb0*lb0);
        float i1 = 1.f / (fa1*l1 + fb1*lb1);
        float* Ob = O + ((long long)z*NR + qblk*128)*128;
        #pragma unroll
        for (int ni = 0; ni < 16; ni++) {
            int col = ni*8 + tig*2;
            float o00 = (fa0*acc_o[ni][0] + fb0*msm[r0*MO_ROW + col])     * i0;
            float o01 = (fa0*acc_o[ni][1] + fb0*msm[r0*MO_ROW + col + 1]) * i0;
            float o10 = (fa1*acc_o[ni][2] + fb1*msm[r1*MO_ROW + col])     * i1;
            float o11 = (fa1*acc_o[ni][3] + fb1*msm[r1*MO_ROW + col + 1]) * i1;
            *(float2*)&Ob[(long long)r0*128 + col] = make_float2(o00, o01);
            *(float2*)&Ob[(long long)r1*128 + col] = make_float2(o10, o11);
        }
    }
}

// ======================= combine + headnorm ==================================
__global__ void combine_headnorm(const float* __restrict__ O,
                                 const float* __restrict__ lamp,
                                 const float* __restrict__ hw,
                                 __half* __restrict__ y)
{
    int gw   = (blockIdx.x*blockDim.x + threadIdx.x) >> 5;
    int lane = threadIdx.x & 31;
    if (gw >= 32*NR) return;
    const float4* r1 = (const float4*)(O + (long long)gw*128);
    const float4* r2 = (const float4*)(O + (long long)(32*NR + gw)*128);
    float4 a = r1[lane], b4 = r2[lane];
    float lam = lamp[0];
    float d0 = a.x - lam*b4.x, d1 = a.y - lam*b4.y;
    float d2 = a.z - lam*b4.z, d3 = a.w - lam*b4.w;
    float ssq = d0*d0 + d1*d1 + d2*d2 + d3*d3;
    #pragma unroll
    for (int o = 16; o; o >>= 1) ssq += __shfl_xor_sync(0xffffffffu, ssq, o);
    float inv = (1.f - LAMBDA_INIT) * rsqrtf(ssq*(1.f/128.f) + EPS);
    float4 w = ((const float4*)hw)[lane];
    ushort4 hh;
    hh.x = h1(d0*inv*w.x); hh.y = h1(d1*inv*w.y);
    hh.z = h1(d2*inv*w.z); hh.w = h1(d3*inv*w.w);
    int bh = gw >> 9, i = gw & 511;
    int b = bh >> 3, h = bh & 7;
    ((ushort4*)y)[(long long)(b*NR + i)*256 + h*32 + lane] = hh;
}

// ======================= elementwise kernels =================================
__global__ void downsample_h(const float4* __restrict__ x, ushort4* __restrict__ xd)
{
    int idx = blockIdx.x*blockDim.x + threadIdx.x;
    if (idx >= NB*NR*NC/4) return;
    int c4 = idx & 255, bi = idx >> 8;
    int i = bi & (NR-1), b = bi >> 9;
    long long row = (long long)b*NL + 8*i + 3;
    float4 p = x[row*256 + c4], q = x[(row+1)*256 + c4];
    ushort4 h;
    h.x = h1(0.5f*(p.x+q.x)); h.y = h1(0.5f*(p.y+q.y));
    h.z = h1(0.5f*(p.z+q.z)); h.w = h1(0.5f*(p.w+q.w));
    xd[idx] = h;
}

__global__ void convert4(const float4* __restrict__ Wq, const float4* __restrict__ Wk,
                         const float4* __restrict__ Wv, const float4* __restrict__ Wo,
                         ushort4* __restrict__ w3, ushort4* __restrict__ wo)
{
    int idx = blockIdx.x*blockDim.x + threadIdx.x;
    if (idx >= NC*NC/4) return;
    const float4* s; ushort4* d; int off = 0;
    switch (blockIdx.y) {
        case 0: s = Wq; d = w3; off = 0;          break;
        case 1: s = Wk; d = w3; off = NC*NC/4;    break;
        case 2: s = Wv; d = w3; off = 2*(NC*NC/4);break;
        default:s = Wo; d = wo; off = 0;          break;
    }
    float4 v = s[idx];
    ushort4 h;
    h.x = h1(v.x); h.y = h1(v.y); h.z = h1(v.z); h.w = h1(v.w);
    d[off + idx] = h;
}

__global__ void lambda_kernel(const float* lq1, const float* lk1,
                              const float* lq2, const float* lk2, float* out)
{
    int t = threadIdx.x;
    float a = lq1[t]*lk1[t] + lq1[t+32]*lk1[t+32];
    float b = lq2[t]*lk2[t] + lq2[t+32]*lk2[t+32];
    #pragma unroll
    for (int o = 16; o; o >>= 1) {
        a += __shfl_xor_sync(0xffffffffu, a, o);
        b += __shfl_xor_sync(0xffffffffu, b, o);
    }
    if (t == 0) out[0] = expf(a) - expf(b) + LAMBDA_INIT;
}

// upsample 512 -> 4096
__global__ void upsample_kernel(const float4* __restrict__ lr, float4* __restrict__ out)
{
    int idx = blockIdx.x*blockDim.x + threadIdx.x;
    if (idx >= NB*NL*NC/4) return;
    int c4 = idx & 255, j = (idx >> 8) & (NL-1), b = idx >> 20;
    float coords = fminf(fmaxf(((float)j + 0.5f)*0.125f - 0.5f, 0.f), 511.f);
    int lo = (int)coords;
    int hi = min(lo + 1, 511);
    float w = coords - (float)lo, w0 = 1.f - w;
    long long base = (long long)b * NR * 256;
    float4 a = lr[base + (long long)lo*256 + c4];
    float4 c = lr[base + (long long)hi*256 + c4];
    float4 o;
    o.x = a.x*w0 + c.x*w; o.y = a.y*w0 + c.y*w;
    o.z = a.z*w0 + c.z*w; o.w = a.w*w0 + c.w*w;
    out[idx] = o;
}

// ======================= host launcher =======================================
extern "C" void kernel_launch(void* const* d_in, const int* in_sizes, int n_in,
                              void* d_out, int out_size)
{
    const float* x   = (const float*)d_in[0];
    const float* Wq  = (const float*)d_in[1];
    const float* Wk  = (const float*)d_in[2];
    const float* Wv  = (const float*)d_in[3];
    const float* Wo  = (const float*)d_in[4];
    const float* qw  = (const float*)d_in[5];
    const float* kw  = (const float*)d_in[6];
    const float* hw  = (const float*)d_in[7];
    const float* lq1 = (const float*)d_in[8];
    const float* lk1 = (const float*)d_in[9];
    const float* lq2 = (const float*)d_in[10];
    const float* lk2 = (const float*)d_in[11];

    float* full_out = (float*)d_out;
    float* lowrank  = full_out + (size_t)NB*NL*NC;

    #define GS(p, s) cudaGetSymbolAddress((void**)&p, s)
    __half *xd,*W,*Wo_,*q12,*k12,*vt,*y;
    float *ob,*lam;
    GS(xd,g_xd); GS(W,g_W); GS(Wo_,g_Wo);
    GS(q12,g_q12); GS(k12,g_k12); GS(vt,g_vt);
    GS(ob,g_o); GS(y,g_y); GS(lam,g_lam);
    #undef GS

    cudaFuncSetAttribute(gemm_mma, cudaFuncAttributeMaxDynamicSharedMemorySize, GEMM_SMEM);
    cudaFuncSetAttribute(flash_attn, cudaFuncAttributeMaxDynamicSharedMemorySize, FLASH_SMEM);

    // 1. downsample + fp16; weights fp16; lambda
    downsample_h<<<(NB*NR*NC/4 + 255)/256, 256>>>((const float4*)x, (ushort4*)xd);
    dim3 gcv((NC*NC/4 + 255)/256, 4);
    convert4<<<gcv, 256>>>((const float4*)Wq, (const float4*)Wk,
                           (const float4*)Wv, (const float4*)Wo,
                           (ushort4*)W, (ushort4*)Wo_);
    lambda_kernel<<<1, 32>>>(lq1, lk1, lq2, lk2, lam);

    // 2. QKV projections with fused normrope (z<2) / v-transpose (z=2) epilogues
    dim3 gqkv(NC/128, (NB*NR)/128, 3);
    gemm_mma<<<gqkv, 256, GEMM_SMEM>>>(xd, W, nullptr, NB*NR, NC, NC,
        0, (long long)NC*NC, 0, 1.f, 3, qw, kw);

    // 3. fused attention (scores + softmax + PV, online, key-split warps) -> g_o
    dim3 gfa(1, NR/128, 2*NB*NH);
    flash_attn<<<gfa, 512, FLASH_SMEM>>>(q12, k12, vt, ob);

    // 4. combine (O1 - lam*O2) + head rmsnorm -> y fp16
    combine_headnorm<<<(32*NR*32 + 255)/256, 256>>>(ob, lam, hw, y);

    // 5. Wo projection + fused silu -> lowrank_out
    dim3 gwo(NC/128, (NB*NR)/128, 1);
    gemm_mma<<<gwo, 256, GEMM_SMEM>>>(y, Wo_, lowrank, NB*NR, NC, NC,
        0, 0, 0, 1.f, 1, nullptr, nullptr);

    // 6. upsample -> full_out
    upsample_kernel<<<(NB*NL*NC/4 + 255)/256, 256>>>((const float4*)lowrank, (float4*)full_out);
}

// round 15
// speedup vs baseline: 1.0342x; 1.0342x over previous
#include <cuda_runtime.h>
#include <cuda_fp16.h>
#include <math.h>
#include <stdint.h>

#define NB 4
#define NL 4096
#define NC 1024
#define NH 8
#define NR 512
#define ND 64
#define LAMBDA_INIT 0.8f
#define EPS 1e-6f

#define SZQ   (NB*NH*NR*ND)

// ======================= device scratch (no allocs allowed) ==================
__device__ __half g_xd [NB*NR*NC];
__device__ __half g_W  [3*NC*NC];          // Wq,Wk,Wv
__device__ __half g_Wo [NC*NC];
__device__ __half g_q12[2*SZQ];
__device__ __half g_k12[2*SZQ];
__device__ __half g_vt [NB*NH*128*NR];
__device__ float  g_o  [2*NB*NH*NR*128];   // O1 | O2 (fp32)
__device__ __half g_y  [NB*NR*NC];
__device__ float  g_lam[1];

// ======================= asm helpers =========================================
__device__ __forceinline__ uint32_t smem_u32(const void* p){
    uint32_t a;
    asm("{ .reg .u64 t; cvta.to.shared.u64 t, %1; cvt.u32.u64 %0, t; }" : "=r"(a) : "l"(p));
    return a;
}
__device__ __forceinline__ void cpa16(uint32_t d, const void* s){
    asm volatile("cp.async.cg.shared.global [%0], [%1], 16;" :: "r"(d), "l"(s));
}
#define CP_COMMIT() asm volatile("cp.async.commit_group;" ::: "memory")
#define CP_WAIT0()  asm volatile("cp.async.wait_group 0;" ::: "memory")
#define CP_WAIT1()  asm volatile("cp.async.wait_group 1;" ::: "memory")

__device__ __forceinline__ void mma16816(float* c,
    uint32_t a0, uint32_t a1, uint32_t a2, uint32_t a3, uint32_t b0, uint32_t b1)
{
    asm volatile(
        "mma.sync.aligned.m16n8k16.row.col.f32.f16.f16.f32 "
        "{%0,%1,%2,%3}, {%4,%5,%6,%7}, {%8,%9}, {%0,%1,%2,%3};"
        : "+f"(c[0]), "+f"(c[1]), "+f"(c[2]), "+f"(c[3])
        : "r"(a0), "r"(a1), "r"(a2), "r"(a3), "r"(b0), "r"(b1));
}
#define LDSM4(r0,r1,r2,r3, addr) \
    asm volatile("ldmatrix.sync.aligned.m8n8.x4.shared.b16 {%0,%1,%2,%3}, [%4];" \
        : "=r"(r0),"=r"(r1),"=r"(r2),"=r"(r3) : "r"(addr))

__device__ __forceinline__ unsigned short h1(float v){
    return __half_as_ushort(__float2half_rn(v));
}
__device__ __forceinline__ uint32_t pk2(float a, float b){
    __half2 h = __floats2half2_rn(a, b);
    return *(uint32_t*)&h;
}

// ======================= HMMA fp16 batched NT GEMM (R10 config) ==============
#define ROW_B   144
#define TILE_B  (128*ROW_B)          // 18432
#define STG_B   (2*TILE_B)           // 36864
#define GEMM_SMEM (3*STG_B)          // 110592

__device__ __forceinline__ void ld_stage(uint32_t sbase, int tid, long long c64,
    const __half* Ab, const __half* Bb, int K)
{
    int seg = tid & 7;
    #pragma unroll
    for (int it = 0; it < 8; it++) {
        int i = tid + it*256;
        int r = (i >> 3) & 127;
        const __half* src = (it < 4) ? Ab : Bb;
        cpa16(sbase + (it >> 2)*TILE_B + r*ROW_B + seg*16,
              src + (long long)r*K + c64 + seg*8);
    }
    CP_COMMIT();
}

__global__ __launch_bounds__(256, 2)
void gemm_mma(const __half* __restrict__ A, const __half* __restrict__ B,
              float* __restrict__ C, int M, int N, int K,
              long long sA, long long sB, long long sC, float alpha, int mode,
              const float* __restrict__ w1, const float* __restrict__ w2)
{
    extern __shared__ char sm[];
    uint32_t sb = smem_u32(sm);
    const int tid  = threadIdx.x;
    const int wid  = tid >> 5, lane = tid & 31;
    const int gid  = lane >> 2, tig = lane & 3;
    const int wm   = (wid & 1) * 64;
    const int wn   = (wid >> 1) * 32;
    const int bm   = blockIdx.y * 128, bn = blockIdx.x * 128;
    const int z    = blockIdx.z;

    const __half* Ab = A + z*sA + (long long)bm*K;
    const __half* Bb = B + z*sB + (long long)bn*K;

    const int a_row = (lane & 7) + ((lane & 8)  ? 8 : 0);
    const int a_col = (lane & 16) ? 16 : 0;
    const int b_row = (lane & 7) + ((lane & 16) ? 8 : 0);
    const int b_col = (lane & 8)  ? 16 : 0;

    float acc[4][4][4];
    #pragma unroll
    for (int mi = 0; mi < 4; mi++)
        #pragma unroll
        for (int ni = 0; ni < 4; ni++)
            #pragma unroll
            for (int t = 0; t < 4; t++) acc[mi][ni][t] = 0.f;

    const int nch = K >> 6;
    ld_stage(sb, tid, 0, Ab, Bb, K);
    if (nch > 1) ld_stage(sb + STG_B, tid, 64, Ab, Bb, K);

    for (int c = 0; c < nch; c++) {
        if (c + 1 < nch) CP_WAIT1(); else CP_WAIT0();
        __syncthreads();
        if (c + 2 < nch)
            ld_stage(sb + ((c + 2) % 3)*STG_B, tid, (long long)(c + 2)*64, Ab, Bb, K);

        const uint32_t p  = sb + (c % 3)*STG_B;
        const uint32_t pA = p, pB = p + TILE_B;

        #pragma unroll
        for (int kk = 0; kk < 4; kk++) {
            const int ko = kk*32;
            uint32_t bh[4][2];
            #pragma unroll
            for (int nj = 0; nj < 2; nj++) {
                uint32_t bd = pB + (wn + nj*16 + b_row)*ROW_B + ko + b_col;
                LDSM4(bh[2*nj][0], bh[2*nj][1], bh[2*nj+1][0], bh[2*nj+1][1], bd);
            }
            #pragma unroll
            for (int mi = 0; mi < 4; mi++) {
                uint32_t ah[4];
                uint32_t ad = pA + (wm + mi*16 + a_row)*ROW_B + ko + a_col;
                LDSM4(ah[0], ah[1], ah[2], ah[3], ad);
                #pragma unroll
                for (int ni = 0; ni < 4; ni++)
                    mma16816(acc[mi][ni], ah[0], ah[1], ah[2], ah[3],
                             bh[ni][0], bh[ni][1]);
            }
        }
    }

    if (mode == 0 || mode == 1) {
        float* Cb = C + z*sC;
        #pragma unroll
        for (int mi = 0; mi < 4; mi++) {
            #pragma unroll
            for (int ni = 0; ni < 4; ni++) {
                int row = bm + wm + mi*16 + gid;
                int col = bn + wn + ni*8 + tig*2;
                float v0 = acc[mi][ni][0]*alpha, v1 = acc[mi][ni][1]*alpha;
                float v2 = acc[mi][ni][2]*alpha, v3 = acc[mi][ni][3]*alpha;
                if (mode == 1) {
                    v0 /= (1.f + __expf(-v0)); v1 /= (1.f + __expf(-v1));
                    v2 /= (1.f + __expf(-v2)); v3 /= (1.f + __expf(-v3));
                }
                *(float2*)&Cb[(long long)row*N + col]       = make_float2(v0, v1);
                *(float2*)&Cb[(long long)(row + 8)*N + col] = make_float2(v2, v3);
            }
        }
        return;
    }

    // ---------- mode 3: fused QKV epilogue (stage to smem first) --------------
    __syncthreads();
    float* esm = (float*)sm;                    // 128 x 132 floats
    const bool vtr = (z == 2);
    #pragma unroll
    for (int mi = 0; mi < 4; mi++) {
        #pragma unroll
        for (int ni = 0; ni < 4; ni++) {
            int r0 = wm + mi*16 + gid;
            int cc = wn + ni*8 + tig*2;
            if (vtr) {
                esm[cc*132 + r0]         = acc[mi][ni][0];
                esm[(cc+1)*132 + r0]     = acc[mi][ni][1];
                esm[cc*132 + r0 + 8]     = acc[mi][ni][2];
                esm[(cc+1)*132 + r0 + 8] = acc[mi][ni][3];
            } else {
                esm[r0*132 + cc]         = acc[mi][ni][0];
                esm[r0*132 + cc + 1]     = acc[mi][ni][1];
                esm[(r0+8)*132 + cc]     = acc[mi][ni][2];
                esm[(r0+8)*132 + cc + 1] = acc[mi][ni][3];
            }
        }
    }
    __syncthreads();

    const int h = blockIdx.x;              // tile cols = one head
    if (z < 2) {
        const float* w = z ? w2 : w1;
        const int gidx = lane & 15, sgi = lane >> 4;
        const int dmb = (gidx & 7) * 4;
        float4 wv = ((const float4*)w)[gidx];
        float sn[4], cs[4];
        #pragma unroll
        for (int j = 0; j < 4; j++) {
            float f = exp2f(-0.41524101186351494f * (float)(dmb + j));
            __sincosf((float)h * f, &sn[j], &cs[j]);
        }
        __half* dh = (z == 0 ? g_q12 : g_k12) + (long long)sgi*SZQ;
        const bool lo = (gidx & 8) == 0;
        for (int r = wid; r < 128; r += 8) {
            float4 xv = *(float4*)&esm[r*132 + sgi*64 + gidx*4];
            float ssq = xv.x*xv.x + xv.y*xv.y + xv.z*xv.z + xv.w*xv.w;
            #pragma unroll
            for (int o = 8; o; o >>= 1) ssq += __shfl_xor_sync(0xffffffffu, ssq, o);
            float inv = rsqrtf(ssq*(1.f/64.f) + EPS);
            float n0 = xv.x*inv*wv.x, n1 = xv.y*inv*wv.y;
            float n2 = xv.z*inv*wv.z, n3 = xv.w*inv*wv.w;
            float p0 = __shfl_xor_sync(0xffffffffu, n0, 8);
            float p1 = __shfl_xor_sync(0xffffffffu, n1, 8);
            float p2 = __shfl_xor_sync(0xffffffffu, n2, 8);
            float p3 = __shfl_xor_sync(0xffffffffu, n3, 8);
            ushort4 hh;
            hh.x = h1(lo ? n0*cs[0] - p0*sn[0] : p0*sn[0] + n0*cs[0]);
            hh.y = h1(lo ? n1*cs[1] - p1*sn[1] : p1*sn[1] + n1*cs[1]);
            hh.z = h1(lo ? n2*cs[2] - p2*sn[2] : p2*sn[2] + n2*cs[2]);
            hh.w = h1(lo ? n3*cs[3] - p3*sn[3] : p3*sn[3] + n3*cs[3]);
            int tok = bm + r, b = tok >> 9, il = tok & 511;
            long long off = ((long long)((b*NH + h)*NR) + il)*64 + gidx*4;
            *(ushort4*)(dh + off) = hh;
        }
    } else {
        const int b = bm >> 9, ibase = bm & 511;
        const int bh2 = b*NH + h;
        #pragma unroll
        for (int it = 0; it < 32; it++) {
            int e = tid + it*256;
            int cix = e >> 6, ip = e & 63, i = ip*2;
            float2 vv = *(float2*)&esm[cix*132 + i];
            long long o = ((long long)(bh2*128 + cix))*NR + ibase + i;
            *(ushort2*)(g_vt + o) = make_ushort2(h1(vv.x), h1(vv.y));
        }
    }
}

// ======================= fused flash attention (single wave) =================
// grid: (1, 2, 64)  z = s*32 + bh, qblk covers 256 rows.  512 thr = 16 warps,
// each warp owns 16 rows and processes chunks of 128 keys in two sequential
// 64-key halves (keeps transient score regs at 32).
#define FQ_ROW 144
#define FV_ROW 272
#define FK_B   (128*FQ_ROW)      // 18432
#define FV_B   (128*FV_ROW)      // 34816
#define FSTG   (FK_B + FV_B)     // 53248
#define FQ_B   (256*FQ_ROW)      // 36864
#define FLASH_SMEM (FQ_B + 2*FSTG)  // 143360

__device__ __forceinline__ void flash_ld(uint32_t dst, int tid, int j,
    const __half* Kg, const __half* Vg)
{
    #pragma unroll
    for (int t = 0; t < 2; t++) {                    // K-chunk: 128 x 64
        int i = tid + t*512;
        int r = i >> 3, seg = i & 7;
        cpa16(dst + r*FQ_ROW + seg*16, Kg + (long long)(j*128 + r)*64 + seg*8);
    }
    #pragma unroll
    for (int t = 0; t < 4; t++) {                    // V-chunk: 128c x 128i
        int i = tid + t*512;
        int c = i >> 4, sg = i & 15;
        cpa16(dst + FK_B + c*FV_ROW + sg*16, Vg + (long long)c*NR + j*128 + sg*8);
    }
    CP_COMMIT();
}

__global__ __launch_bounds__(512, 1)
void flash_attn(const __half* __restrict__ q12, const __half* __restrict__ k12,
                const __half* __restrict__ vt, float* __restrict__ O)
{
    extern __shared__ char sm[];
    uint32_t sb = smem_u32(sm);
    const uint32_t sQ = sb;
    const int tid = threadIdx.x, wid = tid >> 5, lane = tid & 31;
    const int gid = lane >> 2, tig = lane & 3;
    const int wq = wid * 16;                     // warp's rows within 256-block
    const int z = blockIdx.z, s = z >> 5, bh = z & 31;
    const int qblk = blockIdx.y;                 // 0..1 (256 rows each)

    const __half* Qg = q12 + (long long)s*SZQ + ((long long)(bh*NR) + qblk*256)*64;
    const __half* Kg = k12 + (long long)s*SZQ + (long long)(bh*NR)*64;
    const __half* Vg = vt  + (long long)bh*128*NR;

    // load Q 256x64 (grouped with chunk 0)
    #pragma unroll
    for (int t = 0; t < 4; t++) {
        int i = tid + t*512;
        int r = i >> 3, seg = i & 7;
        cpa16(sQ + r*FQ_ROW + seg*16, Qg + (long long)r*64 + seg*8);
    }
    flash_ld(sQ + FQ_B, tid, 0, Kg, Vg);

    const int a_row = (lane & 7) + ((lane & 8)  ? 8 : 0);
    const int a_col = (lane & 16) ? 16 : 0;
    const int b_row = (lane & 7) + ((lane & 16) ? 8 : 0);
    const int b_col = (lane & 8)  ? 16 : 0;

    float acc_o[16][4];
    #pragma unroll
    for (int ni = 0; ni < 16; ni++)
        #pragma unroll
        for (int t = 0; t < 4; t++) acc_o[ni][t] = 0.f;
    float m0 = -1e30f, m1 = -1e30f, l0 = 0.f, l1 = 0.f;

    for (int j = 0; j < 4; j++) {
        __syncthreads();
        if (j + 1 < 4)
            flash_ld(sQ + FQ_B + ((j + 1) & 1)*FSTG, tid, j + 1, Kg, Vg);
        if (j + 1 < 4) CP_WAIT1(); else CP_WAIT0();
        __syncthreads();

        const uint32_t pK = sQ + FQ_B + (j & 1)*FSTG;
        const uint32_t pV = pK + FK_B;

        #pragma unroll
        for (int kh = 0; kh < 2; kh++) {         // two 64-key halves
            // ---- S = 0.125 * Q K^T (16 rows x 64 keys) ----
            float sc[8][4];
            #pragma unroll
            for (int ni = 0; ni < 8; ni++)
                #pragma unroll
                for (int t = 0; t < 4; t++) sc[ni][t] = 0.f;
            #pragma unroll
            for (int kd = 0; kd < 4; kd++) {
                uint32_t ah[4];
                uint32_t ad = sQ + (wq + a_row)*FQ_ROW + kd*32 + a_col;
                LDSM4(ah[0], ah[1], ah[2], ah[3], ad);
                #pragma unroll
                for (int nj = 0; nj < 4; nj++) {
                    uint32_t b0, b1, b2, b3;
                    uint32_t bd = pK + (kh*64 + nj*16 + b_row)*FQ_ROW + kd*32 + b_col;
                    LDSM4(b0, b1, b2, b3, bd);
                    mma16816(sc[2*nj],   ah[0], ah[1], ah[2], ah[3], b0, b1);
                    mma16816(sc[2*nj+1], ah[0], ah[1], ah[2], ah[3], b2, b3);
                }
            }
            #pragma unroll
            for (int ni = 0; ni < 8; ni++)
                #pragma unroll
                for (int t = 0; t < 4; t++) sc[ni][t] *= 0.125f;

            // ---- online softmax update ----
            float cm0 = -1e30f, cm1 = -1e30f;
            #pragma unroll
            for (int ni = 0; ni < 8; ni++) {
                cm0 = fmaxf(cm0, fmaxf(sc[ni][0], sc[ni][1]));
                cm1 = fmaxf(cm1, fmaxf(sc[ni][2], sc[ni][3]));
            }
            cm0 = fmaxf(cm0, __shfl_xor_sync(0xffffffffu, cm0, 1));
            cm0 = fmaxf(cm0, __shfl_xor_sync(0xffffffffu, cm0, 2));
            cm1 = fmaxf(cm1, __shfl_xor_sync(0xffffffffu, cm1, 1));
            cm1 = fmaxf(cm1, __shfl_xor_sync(0xffffffffu, cm1, 2));
            float nm0 = fmaxf(m0, cm0), nm1 = fmaxf(m1, cm1);
            float f0 = __expf(m0 - nm0), f1 = __expf(m1 - nm1);
            m0 = nm0; m1 = nm1;

            uint32_t ph[4][4];
            float s0 = 0.f, s1 = 0.f;
            #pragma unroll
            for (int t = 0; t < 4; t++) {
                float e00 = __expf(sc[2*t][0]  - nm0), e01 = __expf(sc[2*t][1]  - nm0);
                float e02 = __expf(sc[2*t][2]  - nm1), e03 = __expf(sc[2*t][3]  - nm1);
                float e10 = __expf(sc[2*t+1][0]- nm0), e11 = __expf(sc[2*t+1][1]- nm0);
                float e12 = __expf(sc[2*t+1][2]- nm1), e13 = __expf(sc[2*t+1][3]- nm1);
                s0 += e00 + e01 + e10 + e11;
                s1 += e02 + e03 + e12 + e13;
                ph[t][0] = pk2(e00, e01);
                ph[t][1] = pk2(e02, e03);
                ph[t][2] = pk2(e10, e11);
                ph[t][3] = pk2(e12, e13);
            }
            s0 += __shfl_xor_sync(0xffffffffu, s0, 1);
            s0 += __shfl_xor_sync(0xffffffffu, s0, 2);
            s1 += __shfl_xor_sync(0xffffffffu, s1, 1);
            s1 += __shfl_xor_sync(0xffffffffu, s1, 2);
            l0 = l0*f0 + s0;
            l1 = l1*f1 + s1;

            #pragma unroll
            for (int ni = 0; ni < 16; ni++) {
                acc_o[ni][0] *= f0; acc_o[ni][1] *= f0;
                acc_o[ni][2] *= f1; acc_o[ni][3] *= f1;
            }

            // ---- O += P V (this half's 64 keys, all 128 cols) ----
            #pragma unroll
            for (int t = 0; t < 4; t++) {
                #pragma unroll
                for (int nj = 0; nj < 8; nj++) {
                    uint32_t b0, b1, b2, b3;
                    uint32_t bd = pV + (nj*16 + b_row)*FV_ROW + (kh*64 + t*16)*2 + b_col;
                    LDSM4(b0, b1, b2, b3, bd);
                    mma16816(acc_o[2*nj],   ph[t][0], ph[t][1], ph[t][2], ph[t][3], b0, b1);
                    mma16816(acc_o[2*nj+1], ph[t][0], ph[t][1], ph[t][2], ph[t][3], b2, b3);
                }
            }
        }
    }

    // normalize and write O
    float i0 = 1.f / l0, i1 = 1.f / l1;
    float* Ob = O + ((long long)z*NR + qblk*256)*128;
    #pragma unroll
    for (int ni = 0; ni < 16; ni++) {
        int col = ni*8 + tig*2;
        int r0 = wq + gid;
        *(float2*)&Ob[(long long)r0*128 + col] =
            make_float2(acc_o[ni][0]*i0, acc_o[ni][1]*i0);
        *(float2*)&Ob[(long long)(r0+8)*128 + col] =
            make_float2(acc_o[ni][2]*i1, acc_o[ni][3]*i1);
    }
}

// ======================= combine + headnorm ==================================
__global__ void combine_headnorm(const float* __restrict__ O,
                                 const float* __restrict__ lamp,
                                 const float* __restrict__ hw,
                                 __half* __restrict__ y)
{
    int gw   = (blockIdx.x*blockDim.x + threadIdx.x) >> 5;
    int lane = threadIdx.x & 31;
    if (gw >= 32*NR) return;
    const float4* r1 = (const float4*)(O + (long long)gw*128);
    const float4* r2 = (const float4*)(O + (long long)(32*NR + gw)*128);
    float4 a = r1[lane], b4 = r2[lane];
    float lam = lamp[0];
    float d0 = a.x - lam*b4.x, d1 = a.y - lam*b4.y;
    float d2 = a.z - lam*b4.z, d3 = a.w - lam*b4.w;
    float ssq = d0*d0 + d1*d1 + d2*d2 + d3*d3;
    #pragma unroll
    for (int o = 16; o; o >>= 1) ssq += __shfl_xor_sync(0xffffffffu, ssq, o);
    float inv = (1.f - LAMBDA_INIT) * rsqrtf(ssq*(1.f/128.f) + EPS);
    float4 w = ((const float4*)hw)[lane];
    ushort4 hh;
    hh.x = h1(d0*inv*w.x); hh.y = h1(d1*inv*w.y);
    hh.z = h1(d2*inv*w.z); hh.w = h1(d3*inv*w.w);
    int bh = gw >> 9, i = gw & 511;
    int b = bh >> 3, h = bh & 7;
    ((ushort4*)y)[(long long)(b*NR + i)*256 + h*32 + lane] = hh;
}

// ======================= elementwise kernels =================================
__global__ void downsample_h(const float4* __restrict__ x, ushort4* __restrict__ xd)
{
    int idx = blockIdx.x*blockDim.x + threadIdx.x;
    if (idx >= NB*NR*NC/4) return;
    int c4 = idx & 255, bi = idx >> 8;
    int i = bi & (NR-1), b = bi >> 9;
    long long row = (long long)b*NL + 8*i + 3;
    float4 p = x[row*256 + c4], q = x[(row+1)*256 + c4];
    ushort4 h;
    h.x = h1(0.5f*(p.x+q.x)); h.y = h1(0.5f*(p.y+q.y));
    h.z = h1(0.5f*(p.z+q.z)); h.w = h1(0.5f*(p.w+q.w));
    xd[idx] = h;
}

__global__ void convert4(const float4* __restrict__ Wq, const float4* __restrict__ Wk,
                         const float4* __restrict__ Wv, const float4* __restrict__ Wo,
                         ushort4* __restrict__ w3, ushort4* __restrict__ wo)
{
    int idx = blockIdx.x*blockDim.x + threadIdx.x;
    if (idx >= NC*NC/4) return;
    const float4* s; ushort4* d; int off = 0;
    switch (blockIdx.y) {
        case 0: s = Wq; d = w3; off = 0;          break;
        case 1: s = Wk; d = w3; off = NC*NC/4;    break;
        case 2: s = Wv; d = w3; off = 2*(NC*NC/4);break;
        default:s = Wo; d = wo; off = 0;          break;
    }
    float4 v = s[idx];
    ushort4 h;
    h.x = h1(v.x); h.y = h1(v.y); h.z = h1(v.z); h.w = h1(v.w);
    d[off + idx] = h;
}

__global__ void lambda_kernel(const float* lq1, const float* lk1,
                              const float* lq2, const float* lk2, float* out)
{
    int t = threadIdx.x;
    float a = lq1[t]*lk1[t] + lq1[t+32]*lk1[t+32];
    float b = lq2[t]*lk2[t] + lq2[t+32]*lk2[t+32];
    #pragma unroll
    for (int o = 16; o; o >>= 1) {
        a += __shfl_xor_sync(0xffffffffu, a, o);
        b += __shfl_xor_sync(0xffffffffu, b, o);
    }
    if (t == 0) out[0] = expf(a) - expf(b) + LAMBDA_INIT;
}

// upsample 512 -> 4096
__global__ void upsample_kernel(const float4* __restrict__ lr, float4* __restrict__ out)
{
    int idx = blockIdx.x*blockDim.x + threadIdx.x;
    if (idx >= NB*NL*NC/4) return;
    int c4 = idx & 255, j = (idx >> 8) & (NL-1), b = idx >> 20;
    float coords = fminf(fmaxf(((float)j + 0.5f)*0.125f - 0.5f, 0.f), 511.f);
    int lo = (int)coords;
    int hi = min(lo + 1, 511);
    float w = coords - (float)lo, w0 = 1.f - w;
    long long base = (long long)b * NR * 256;
    float4 a = lr[base + (long long)lo*256 + c4];
    float4 c = lr[base + (long long)hi*256 + c4];
    float4 o;
    o.x = a.x*w0 + c.x*w; o.y = a.y*w0 + c.y*w;
    o.z = a.z*w0 + c.z*w; o.w = a.w*w0 + c.w*w;
    out[idx] = o;
}

// ======================= host launcher =======================================
extern "C" void kernel_launch(void* const* d_in, const int* in_sizes, int n_in,
                              void* d_out, int out_size)
{
    const float* x   = (const float*)d_in[0];
    const float* Wq  = (const float*)d_in[1];
    const float* Wk  = (const float*)d_in[2];
    const float* Wv  = (const float*)d_in[3];
    const float* Wo  = (const float*)d_in[4];
    const float* qw  = (const float*)d_in[5];
    const float* kw  = (const float*)d_in[6];
    const float* hw  = (const float*)d_in[7];
    const float* lq1 = (const float*)d_in[8];
    const float* lk1 = (const float*)d_in[9];
    const float* lq2 = (const float*)d_in[10];
    const float* lk2 = (const float*)d_in[11];

    float* full_out = (float*)d_out;
    float* lowrank  = full_out + (size_t)NB*NL*NC;

    #define GS(p, s) cudaGetSymbolAddress((void**)&p, s)
    __half *xd,*W,*Wo_,*q12,*k12,*vt,*y;
    float *ob,*lam;
    GS(xd,g_xd); GS(W,g_W); GS(Wo_,g_Wo);
    GS(q12,g_q12); GS(k12,g_k12); GS(vt,g_vt);
    GS(ob,g_o); GS(y,g_y); GS(lam,g_lam);
    #undef GS

    cudaFuncSetAttribute(gemm_mma, cudaFuncAttributeMaxDynamicSharedMemorySize, GEMM_SMEM);
    cudaFuncSetAttribute(flash_attn, cudaFuncAttributeMaxDynamicSharedMemorySize, FLASH_SMEM);

    // 1. downsample + fp16; weights fp16; lambda
    downsample_h<<<(NB*NR*NC/4 + 255)/256, 256>>>((const float4*)x, (ushort4*)xd);
    dim3 gcv((NC*NC/4 + 255)/256, 4);
    convert4<<<gcv, 256>>>((const float4*)Wq, (const float4*)Wk,
                           (const float4*)Wv, (const float4*)Wo,
                           (ushort4*)W, (ushort4*)Wo_);
    lambda_kernel<<<1, 32>>>(lq1, lk1, lq2, lk2, lam);

    // 2. QKV projections with fused normrope (z<2) / v-transpose (z=2) epilogues
    dim3 gqkv(NC/128, (NB*NR)/128, 3);
    gemm_mma<<<gqkv, 256, GEMM_SMEM>>>(xd, W, nullptr, NB*NR, NC, NC,
        0, (long long)NC*NC, 0, 1.f, 3, qw, kw);

    // 3. fused attention (single wave: 128 CTAs x 512 thr) -> g_o
    dim3 gfa(1, NR/256, 2*NB*NH);
    flash_attn<<<gfa, 512, FLASH_SMEM>>>(q12, k12, vt, ob);

    // 4. combine (O1 - lam*O2) + head rmsnorm -> y fp16
    combine_headnorm<<<(32*NR*32 + 255)/256, 256>>>(ob, lam, hw, y);

    // 5. Wo projection + fused silu -> lowrank_out
    dim3 gwo(NC/128, (NB*NR)/128, 1);
    gemm_mma<<<gwo, 256, GEMM_SMEM>>>(y, Wo_, lowrank, NB*NR, NC, NC,
        0, 0, 0, 1.f, 1, nullptr, nullptr);

    // 6. upsample -> full_out
    upsample_kernel<<<(NB*NL*NC/4 + 255)/256, 256>>>((const float4*)lowrank, (float4*)full_out);
}

// round 16
// speedup vs baseline: 1.0485x; 1.0139x over previous
#include <cuda_runtime.h>
#include <cuda_fp16.h>
#include <math.h>
#include <stdint.h>

#define NB 4
#define NL 4096
#define NC 1024
#define NH 8
#define NR 512
#define ND 64
#define LAMBDA_INIT 0.8f
#define EPS 1e-6f

#define SZQ   (NB*NH*NR*ND)

// ======================= device scratch (no allocs allowed) ==================
__device__ __half g_xd [NB*NR*NC];
__device__ __half g_W  [3*NC*NC];          // Wq,Wk,Wv
__device__ __half g_Wo [NC*NC];
__device__ __half g_q12[2*SZQ];
__device__ __half g_k12[2*SZQ];
__device__ __half g_vt [NB*NH*128*NR];
__device__ float  g_o  [2*NB*NH*NR*128];   // O1 | O2 (fp32)
__device__ __half g_y  [NB*NR*NC];
__device__ float  g_lam[1];

// ======================= asm helpers =========================================
__device__ __forceinline__ uint32_t smem_u32(const void* p){
    uint32_t a;
    asm("{ .reg .u64 t; cvta.to.shared.u64 t, %1; cvt.u32.u64 %0, t; }" : "=r"(a) : "l"(p));
    return a;
}
__device__ __forceinline__ void cpa16(uint32_t d, const void* s){
    asm volatile("cp.async.cg.shared.global [%0], [%1], 16;" :: "r"(d), "l"(s));
}
#define CP_COMMIT() asm volatile("cp.async.commit_group;" ::: "memory")
#define CP_WAIT0()  asm volatile("cp.async.wait_group 0;" ::: "memory")
#define CP_WAIT1()  asm volatile("cp.async.wait_group 1;" ::: "memory")

__device__ __forceinline__ void mma16816(float* c,
    uint32_t a0, uint32_t a1, uint32_t a2, uint32_t a3, uint32_t b0, uint32_t b1)
{
    asm volatile(
        "mma.sync.aligned.m16n8k16.row.col.f32.f16.f16.f32 "
        "{%0,%1,%2,%3}, {%4,%5,%6,%7}, {%8,%9}, {%0,%1,%2,%3};"
        : "+f"(c[0]), "+f"(c[1]), "+f"(c[2]), "+f"(c[3])
        : "r"(a0), "r"(a1), "r"(a2), "r"(a3), "r"(b0), "r"(b1));
}
#define LDSM4(r0,r1,r2,r3, addr) \
    asm volatile("ldmatrix.sync.aligned.m8n8.x4.shared.b16 {%0,%1,%2,%3}, [%4];" \
        : "=r"(r0),"=r"(r1),"=r"(r2),"=r"(r3) : "r"(addr))

__device__ __forceinline__ unsigned short h1(float v){
    return __half_as_ushort(__float2half_rn(v));
}
__device__ __forceinline__ uint32_t pk2(float a, float b){
    __half2 h = __floats2half2_rn(a, b);
    return *(uint32_t*)&h;
}

// ======================= HMMA fp16 batched NT GEMM (R10 config) ==============
#define ROW_B   144
#define TILE_B  (128*ROW_B)          // 18432
#define STG_B   (2*TILE_B)           // 36864
#define GEMM_SMEM (3*STG_B)          // 110592

__device__ __forceinline__ void ld_stage(uint32_t sbase, int tid, long long c64,
    const __half* Ab, const __half* Bb, int K)
{
    int seg = tid & 7;
    #pragma unroll
    for (int it = 0; it < 8; it++) {
        int i = tid + it*256;
        int r = (i >> 3) & 127;
        const __half* src = (it < 4) ? Ab : Bb;
        cpa16(sbase + (it >> 2)*TILE_B + r*ROW_B + seg*16,
              src + (long long)r*K + c64 + seg*8);
    }
    CP_COMMIT();
}

__global__ __launch_bounds__(256, 2)
void gemm_mma(const __half* __restrict__ A, const __half* __restrict__ B,
              float* __restrict__ C, int M, int N, int K,
              long long sA, long long sB, long long sC, float alpha, int mode,
              const float* __restrict__ w1, const float* __restrict__ w2)
{
    extern __shared__ char sm[];
    uint32_t sb = smem_u32(sm);
    const int tid  = threadIdx.x;
    const int wid  = tid >> 5, lane = tid & 31;
    const int gid  = lane >> 2, tig = lane & 3;
    const int wm   = (wid & 1) * 64;
    const int wn   = (wid >> 1) * 32;
    const int bm   = blockIdx.y * 128, bn = blockIdx.x * 128;
    const int z    = blockIdx.z;

    const __half* Ab = A + z*sA + (long long)bm*K;
    const __half* Bb = B + z*sB + (long long)bn*K;

    const int a_row = (lane & 7) + ((lane & 8)  ? 8 : 0);
    const int a_col = (lane & 16) ? 16 : 0;
    const int b_row = (lane & 7) + ((lane & 16) ? 8 : 0);
    const int b_col = (lane & 8)  ? 16 : 0;

    float acc[4][4][4];
    #pragma unroll
    for (int mi = 0; mi < 4; mi++)
        #pragma unroll
        for (int ni = 0; ni < 4; ni++)
            #pragma unroll
            for (int t = 0; t < 4; t++) acc[mi][ni][t] = 0.f;

    const int nch = K >> 6;
    ld_stage(sb, tid, 0, Ab, Bb, K);
    if (nch > 1) ld_stage(sb + STG_B, tid, 64, Ab, Bb, K);

    for (int c = 0; c < nch; c++) {
        if (c + 1 < nch) CP_WAIT1(); else CP_WAIT0();
        __syncthreads();
        if (c + 2 < nch)
            ld_stage(sb + ((c + 2) % 3)*STG_B, tid, (long long)(c + 2)*64, Ab, Bb, K);

        const uint32_t p  = sb + (c % 3)*STG_B;
        const uint32_t pA = p, pB = p + TILE_B;

        #pragma unroll
        for (int kk = 0; kk < 4; kk++) {
            const int ko = kk*32;
            uint32_t bh[4][2];
            #pragma unroll
            for (int nj = 0; nj < 2; nj++) {
                uint32_t bd = pB + (wn + nj*16 + b_row)*ROW_B + ko + b_col;
                LDSM4(bh[2*nj][0], bh[2*nj][1], bh[2*nj+1][0], bh[2*nj+1][1], bd);
            }
            #pragma unroll
            for (int mi = 0; mi < 4; mi++) {
                uint32_t ah[4];
                uint32_t ad = pA + (wm + mi*16 + a_row)*ROW_B + ko + a_col;
                LDSM4(ah[0], ah[1], ah[2], ah[3], ad);
                #pragma unroll
                for (int ni = 0; ni < 4; ni++)
                    mma16816(acc[mi][ni], ah[0], ah[1], ah[2], ah[3],
                             bh[ni][0], bh[ni][1]);
            }
        }
    }

    if (mode == 0 || mode == 1) {
        float* Cb = C + z*sC;
        #pragma unroll
        for (int mi = 0; mi < 4; mi++) {
            #pragma unroll
            for (int ni = 0; ni < 4; ni++) {
                int row = bm + wm + mi*16 + gid;
                int col = bn + wn + ni*8 + tig*2;
                float v0 = acc[mi][ni][0]*alpha, v1 = acc[mi][ni][1]*alpha;
                float v2 = acc[mi][ni][2]*alpha, v3 = acc[mi][ni][3]*alpha;
                if (mode == 1) {
                    v0 /= (1.f + __expf(-v0)); v1 /= (1.f + __expf(-v1));
                    v2 /= (1.f + __expf(-v2)); v3 /= (1.f + __expf(-v3));
                }
                *(float2*)&Cb[(long long)row*N + col]       = make_float2(v0, v1);
                *(float2*)&Cb[(long long)(row + 8)*N + col] = make_float2(v2, v3);
            }
        }
        return;
    }

    // ---------- mode 3: fused QKV epilogue (stage to smem first) --------------
    __syncthreads();
    float* esm = (float*)sm;                    // 128 x 132 floats
    const bool vtr = (z == 2);
    #pragma unroll
    for (int mi = 0; mi < 4; mi++) {
        #pragma unroll
        for (int ni = 0; ni < 4; ni++) {
            int r0 = wm + mi*16 + gid;
            int cc = wn + ni*8 + tig*2;
            if (vtr) {
                esm[cc*132 + r0]         = acc[mi][ni][0];
                esm[(cc+1)*132 + r0]     = acc[mi][ni][1];
                esm[cc*132 + r0 + 8]     = acc[mi][ni][2];
                esm[(cc+1)*132 + r0 + 8] = acc[mi][ni][3];
            } else {
                esm[r0*132 + cc]         = acc[mi][ni][0];
                esm[r0*132 + cc + 1]     = acc[mi][ni][1];
                esm[(r0+8)*132 + cc]     = acc[mi][ni][2];
                esm[(r0+8)*132 + cc + 1] = acc[mi][ni][3];
            }
        }
    }
    __syncthreads();

    const int h = blockIdx.x;              // tile cols = one head
    if (z < 2) {
        const float* w = z ? w2 : w1;
        const int gidx = lane & 15, sgi = lane >> 4;
        const int dmb = (gidx & 7) * 4;
        float4 wv = ((const float4*)w)[gidx];
        float sn[4], cs[4];
        #pragma unroll
        for (int j = 0; j < 4; j++) {
            float f = exp2f(-0.41524101186351494f * (float)(dmb + j));
            __sincosf((float)h * f, &sn[j], &cs[j]);
        }
        __half* dh = (z == 0 ? g_q12 : g_k12) + (long long)sgi*SZQ;
        const bool lo = (gidx & 8) == 0;
        for (int r = wid; r < 128; r += 8) {
            float4 xv = *(float4*)&esm[r*132 + sgi*64 + gidx*4];
            float ssq = xv.x*xv.x + xv.y*xv.y + xv.z*xv.z + xv.w*xv.w;
            #pragma unroll
            for (int o = 8; o; o >>= 1) ssq += __shfl_xor_sync(0xffffffffu, ssq, o);
            float inv = rsqrtf(ssq*(1.f/64.f) + EPS);
            float n0 = xv.x*inv*wv.x, n1 = xv.y*inv*wv.y;
            float n2 = xv.z*inv*wv.z, n3 = xv.w*inv*wv.w;
            float p0 = __shfl_xor_sync(0xffffffffu, n0, 8);
            float p1 = __shfl_xor_sync(0xffffffffu, n1, 8);
            float p2 = __shfl_xor_sync(0xffffffffu, n2, 8);
            float p3 = __shfl_xor_sync(0xffffffffu, n3, 8);
            ushort4 hh;
            hh.x = h1(lo ? n0*cs[0] - p0*sn[0] : p0*sn[0] + n0*cs[0]);
            hh.y = h1(lo ? n1*cs[1] - p1*sn[1] : p1*sn[1] + n1*cs[1]);
            hh.z = h1(lo ? n2*cs[2] - p2*sn[2] : p2*sn[2] + n2*cs[2]);
            hh.w = h1(lo ? n3*cs[3] - p3*sn[3] : p3*sn[3] + n3*cs[3]);
            int tok = bm + r, b = tok >> 9, il = tok & 511;
            long long off = ((long long)((b*NH + h)*NR) + il)*64 + gidx*4;
            *(ushort4*)(dh + off) = hh;
        }
    } else {
        const int b = bm >> 9, ibase = bm & 511;
        const int bh2 = b*NH + h;
        #pragma unroll
        for (int it = 0; it < 32; it++) {
            int e = tid + it*256;
            int cix = e >> 6, ip = e & 63, i = ip*2;
            float2 vv = *(float2*)&esm[cix*132 + i];
            long long o = ((long long)(bh2*128 + cix))*NR + ibase + i;
            *(ushort2*)(g_vt + o) = make_ushort2(h1(vv.x), h1(vv.y));
        }
    }
}

// ======================= fused flash attention (single wave) =================
#define FQ_ROW 144
#define FV_ROW 272
#define FK_B   (128*FQ_ROW)      // 18432
#define FV_B   (128*FV_ROW)      // 34816
#define FSTG   (FK_B + FV_B)     // 53248
#define FQ_B   (256*FQ_ROW)      // 36864
#define FLASH_SMEM (FQ_B + 2*FSTG)  // 143360

__device__ __forceinline__ void flash_ld(uint32_t dst, int tid, int j,
    const __half* Kg, const __half* Vg)
{
    #pragma unroll
    for (int t = 0; t < 2; t++) {                    // K-chunk: 128 x 64
        int i = tid + t*512;
        int r = i >> 3, seg = i & 7;
        cpa16(dst + r*FQ_ROW + seg*16, Kg + (long long)(j*128 + r)*64 + seg*8);
    }
    #pragma unroll
    for (int t = 0; t < 4; t++) {                    // V-chunk: 128c x 128i
        int i = tid + t*512;
        int c = i >> 4, sg = i & 15;
        cpa16(dst + FK_B + c*FV_ROW + sg*16, Vg + (long long)c*NR + j*128 + sg*8);
    }
    CP_COMMIT();
}

__global__ __launch_bounds__(512, 1)
void flash_attn(const __half* __restrict__ q12, const __half* __restrict__ k12,
                const __half* __restrict__ vt, float* __restrict__ O)
{
    extern __shared__ char sm[];
    uint32_t sb = smem_u32(sm);
    const uint32_t sQ = sb;
    const int tid = threadIdx.x, wid = tid >> 5, lane = tid & 31;
    const int gid = lane >> 2, tig = lane & 3;
    const int wq = wid * 16;
    const int z = blockIdx.z, s = z >> 5, bh = z & 31;
    const int qblk = blockIdx.y;

    const __half* Qg = q12 + (long long)s*SZQ + ((long long)(bh*NR) + qblk*256)*64;
    const __half* Kg = k12 + (long long)s*SZQ + (long long)(bh*NR)*64;
    const __half* Vg = vt  + (long long)bh*128*NR;

    #pragma unroll
    for (int t = 0; t < 4; t++) {
        int i = tid + t*512;
        int r = i >> 3, seg = i & 7;
        cpa16(sQ + r*FQ_ROW + seg*16, Qg + (long long)r*64 + seg*8);
    }
    flash_ld(sQ + FQ_B, tid, 0, Kg, Vg);

    const int a_row = (lane & 7) + ((lane & 8)  ? 8 : 0);
    const int a_col = (lane & 16) ? 16 : 0;
    const int b_row = (lane & 7) + ((lane & 16) ? 8 : 0);
    const int b_col = (lane & 8)  ? 16 : 0;

    float acc_o[16][4];
    #pragma unroll
    for (int ni = 0; ni < 16; ni++)
        #pragma unroll
        for (int t = 0; t < 4; t++) acc_o[ni][t] = 0.f;
    float m0 = -1e30f, m1 = -1e30f, l0 = 0.f, l1 = 0.f;

    for (int j = 0; j < 4; j++) {
        __syncthreads();
        if (j + 1 < 4)
            flash_ld(sQ + FQ_B + ((j + 1) & 1)*FSTG, tid, j + 1, Kg, Vg);
        if (j + 1 < 4) CP_WAIT1(); else CP_WAIT0();
        __syncthreads();

        const uint32_t pK = sQ + FQ_B + (j & 1)*FSTG;
        const uint32_t pV = pK + FK_B;

        #pragma unroll
        for (int kh = 0; kh < 2; kh++) {
            float sc[8][4];
            #pragma unroll
            for (int ni = 0; ni < 8; ni++)
                #pragma unroll
                for (int t = 0; t < 4; t++) sc[ni][t] = 0.f;
            #pragma unroll
            for (int kd = 0; kd < 4; kd++) {
                uint32_t ah[4];
                uint32_t ad = sQ + (wq + a_row)*FQ_ROW + kd*32 + a_col;
                LDSM4(ah[0], ah[1], ah[2], ah[3], ad);
                #pragma unroll
                for (int nj = 0; nj < 4; nj++) {
                    uint32_t b0, b1, b2, b3;
                    uint32_t bd = pK + (kh*64 + nj*16 + b_row)*FQ_ROW + kd*32 + b_col;
                    LDSM4(b0, b1, b2, b3, bd);
                    mma16816(sc[2*nj],   ah[0], ah[1], ah[2], ah[3], b0, b1);
                    mma16816(sc[2*nj+1], ah[0], ah[1], ah[2], ah[3], b2, b3);
                }
            }
            #pragma unroll
            for (int ni = 0; ni < 8; ni++)
                #pragma unroll
                for (int t = 0; t < 4; t++) sc[ni][t] *= 0.125f;

            float cm0 = -1e30f, cm1 = -1e30f;
            #pragma unroll
            for (int ni = 0; ni < 8; ni++) {
                cm0 = fmaxf(cm0, fmaxf(sc[ni][0], sc[ni][1]));
                cm1 = fmaxf(cm1, fmaxf(sc[ni][2], sc[ni][3]));
            }
            cm0 = fmaxf(cm0, __shfl_xor_sync(0xffffffffu, cm0, 1));
            cm0 = fmaxf(cm0, __shfl_xor_sync(0xffffffffu, cm0, 2));
            cm1 = fmaxf(cm1, __shfl_xor_sync(0xffffffffu, cm1, 1));
            cm1 = fmaxf(cm1, __shfl_xor_sync(0xffffffffu, cm1, 2));
            float nm0 = fmaxf(m0, cm0), nm1 = fmaxf(m1, cm1);
            float f0 = __expf(m0 - nm0), f1 = __expf(m1 - nm1);
            m0 = nm0; m1 = nm1;

            uint32_t ph[4][4];
            float s0 = 0.f, s1 = 0.f;
            #pragma unroll
            for (int t = 0; t < 4; t++) {
                float e00 = __expf(sc[2*t][0]  - nm0), e01 = __expf(sc[2*t][1]  - nm0);
                float e02 = __expf(sc[2*t][2]  - nm1), e03 = __expf(sc[2*t][3]  - nm1);
                float e10 = __expf(sc[2*t+1][0]- nm0), e11 = __expf(sc[2*t+1][1]- nm0);
                float e12 = __expf(sc[2*t+1][2]- nm1), e13 = __expf(sc[2*t+1][3]- nm1);
                s0 += e00 + e01 + e10 + e11;
                s1 += e02 + e03 + e12 + e13;
                ph[t][0] = pk2(e00, e01);
                ph[t][1] = pk2(e02, e03);
                ph[t][2] = pk2(e10, e11);
                ph[t][3] = pk2(e12, e13);
            }
            s0 += __shfl_xor_sync(0xffffffffu, s0, 1);
            s0 += __shfl_xor_sync(0xffffffffu, s0, 2);
            s1 += __shfl_xor_sync(0xffffffffu, s1, 1);
            s1 += __shfl_xor_sync(0xffffffffu, s1, 2);
            l0 = l0*f0 + s0;
            l1 = l1*f1 + s1;

            #pragma unroll
            for (int ni = 0; ni < 16; ni++) {
                acc_o[ni][0] *= f0; acc_o[ni][1] *= f0;
                acc_o[ni][2] *= f1; acc_o[ni][3] *= f1;
            }

            #pragma unroll
            for (int t = 0; t < 4; t++) {
                #pragma unroll
                for (int nj = 0; nj < 8; nj++) {
                    uint32_t b0, b1, b2, b3;
                    uint32_t bd = pV + (nj*16 + b_row)*FV_ROW + (kh*64 + t*16)*2 + b_col;
                    LDSM4(b0, b1, b2, b3, bd);
                    mma16816(acc_o[2*nj],   ph[t][0], ph[t][1], ph[t][2], ph[t][3], b0, b1);
                    mma16816(acc_o[2*nj+1], ph[t][0], ph[t][1], ph[t][2], ph[t][3], b2, b3);
                }
            }
        }
    }

    float i0 = 1.f / l0, i1 = 1.f / l1;
    float* Ob = O + ((long long)z*NR + qblk*256)*128;
    #pragma unroll
    for (int ni = 0; ni < 16; ni++) {
        int col = ni*8 + tig*2;
        int r0 = wq + gid;
        *(float2*)&Ob[(long long)r0*128 + col] =
            make_float2(acc_o[ni][0]*i0, acc_o[ni][1]*i0);
        *(float2*)&Ob[(long long)(r0+8)*128 + col] =
            make_float2(acc_o[ni][2]*i1, acc_o[ni][3]*i1);
    }
}

// ======================= combine + headnorm ==================================
__global__ void combine_headnorm(const float* __restrict__ O,
                                 const float* __restrict__ lamp,
                                 const float* __restrict__ hw,
                                 __half* __restrict__ y)
{
    int gw   = (blockIdx.x*blockDim.x + threadIdx.x) >> 5;
    int lane = threadIdx.x & 31;
    if (gw >= 32*NR) return;
    const float4* r1 = (const float4*)(O + (long long)gw*128);
    const float4* r2 = (const float4*)(O + (long long)(32*NR + gw)*128);
    float4 a = r1[lane], b4 = r2[lane];
    float lam = lamp[0];
    float d0 = a.x - lam*b4.x, d1 = a.y - lam*b4.y;
    float d2 = a.z - lam*b4.z, d3 = a.w - lam*b4.w;
    float ssq = d0*d0 + d1*d1 + d2*d2 + d3*d3;
    #pragma unroll
    for (int o = 16; o; o >>= 1) ssq += __shfl_xor_sync(0xffffffffu, ssq, o);
    float inv = (1.f - LAMBDA_INIT) * rsqrtf(ssq*(1.f/128.f) + EPS);
    float4 w = ((const float4*)hw)[lane];
    ushort4 hh;
    hh.x = h1(d0*inv*w.x); hh.y = h1(d1*inv*w.y);
    hh.z = h1(d2*inv*w.z); hh.w = h1(d3*inv*w.w);
    int bh = gw >> 9, i = gw & 511;
    int b = bh >> 3, h = bh & 7;
    ((ushort4*)y)[(long long)(b*NR + i)*256 + h*32 + lane] = hh;
}

// ======================= fused prologue ======================================
// blockIdx.y: 0 = downsample (2048 blocks), 1..4 = weight converts (1024),
//             5 = lambda (1 block)
__global__ void prologue_kernel(const float4* __restrict__ x,
                                const float4* __restrict__ Wq, const float4* __restrict__ Wk,
                                const float4* __restrict__ Wv, const float4* __restrict__ Wo,
                                ushort4* __restrict__ xd,
                                ushort4* __restrict__ w3, ushort4* __restrict__ wo,
                                const float* __restrict__ lq1, const float* __restrict__ lk1,
                                const float* __restrict__ lq2, const float* __restrict__ lk2,
                                float* __restrict__ lam)
{
    const int role = blockIdx.y;
    int idx = blockIdx.x*blockDim.x + threadIdx.x;

    if (role == 0) {
        if (idx >= NB*NR*NC/4) return;
        int c4 = idx & 255, bi = idx >> 8;
        int i = bi & (NR-1), b = bi >> 9;
        long long row = (long long)b*NL + 8*i + 3;
        float4 p = x[row*256 + c4], q = x[(row+1)*256 + c4];
        ushort4 h;
        h.x = h1(0.5f*(p.x+q.x)); h.y = h1(0.5f*(p.y+q.y));
        h.z = h1(0.5f*(p.z+q.z)); h.w = h1(0.5f*(p.w+q.w));
        xd[idx] = h;
    } else if (role <= 4) {
        if (idx >= NC*NC/4) return;
        const float4* s; ushort4* d; int off = 0;
        switch (role) {
            case 1: s = Wq; d = w3; off = 0;          break;
            case 2: s = Wk; d = w3; off = NC*NC/4;    break;
            case 3: s = Wv; d = w3; off = 2*(NC*NC/4);break;
            default:s = Wo; d = wo; off = 0;          break;
        }
        float4 v = s[idx];
        ushort4 h;
        h.x = h1(v.x); h.y = h1(v.y); h.z = h1(v.z); h.w = h1(v.w);
        d[off + idx] = h;
    } else {
        if (blockIdx.x != 0 || threadIdx.x >= 32) return;
        int t = threadIdx.x;
        float a = lq1[t]*lk1[t] + lq1[t+32]*lk1[t+32];
        float b = lq2[t]*lk2[t] + lq2[t+32]*lk2[t+32];
        #pragma unroll
        for (int o = 16; o; o >>= 1) {
            a += __shfl_xor_sync(0xffffffffu, a, o);
            b += __shfl_xor_sync(0xffffffffu, b, o);
        }
        if (t == 0) lam[0] = expf(a) - expf(b) + LAMBDA_INIT;
    }
}

// upsample 512 -> 4096 (2 float4 per thread, shared coord math)
__global__ void upsample_kernel(const float4* __restrict__ lr, float4* __restrict__ out)
{
    int idx = blockIdx.x*blockDim.x + threadIdx.x;
    if (idx >= NB*NL*NC/8) return;
    int c8 = idx & 127, j = (idx >> 7) & (NL-1), b = idx >> 19;
    float coords = fminf(fmaxf(((float)j + 0.5f)*0.125f - 0.5f, 0.f), 511.f);
    int lo = (int)coords;
    int hi = min(lo + 1, 511);
    float w = coords - (float)lo, w0 = 1.f - w;
    long long base = (long long)b * NR * 256;
    long long lrow = base + (long long)lo*256 + c8*2;
    long long hrow = base + (long long)hi*256 + c8*2;
    long long orow = ((long long)(b*NL + j))*256 + c8*2;
    #pragma unroll
    for (int t = 0; t < 2; t++) {
        float4 a = lr[lrow + t];
        float4 c = lr[hrow + t];
        float4 o;
        o.x = a.x*w0 + c.x*w; o.y = a.y*w0 + c.y*w;
        o.z = a.z*w0 + c.z*w; o.w = a.w*w0 + c.w*w;
        out[orow + t] = o;
    }
}

// ======================= host launcher =======================================
extern "C" void kernel_launch(void* const* d_in, const int* in_sizes, int n_in,
                              void* d_out, int out_size)
{
    const float* x   = (const float*)d_in[0];
    const float* Wq  = (const float*)d_in[1];
    const float* Wk  = (const float*)d_in[2];
    const float* Wv  = (const float*)d_in[3];
    const float* Wo  = (const float*)d_in[4];
    const float* qw  = (const float*)d_in[5];
    const float* kw  = (const float*)d_in[6];
    const float* hw  = (const float*)d_in[7];
    const float* lq1 = (const float*)d_in[8];
    const float* lk1 = (const float*)d_in[9];
    const float* lq2 = (const float*)d_in[10];
    const float* lk2 = (const float*)d_in[11];

    float* full_out = (float*)d_out;
    float* lowrank  = full_out + (size_t)NB*NL*NC;

    #define GS(p, s) cudaGetSymbolAddress((void**)&p, s)
    __half *xd,*W,*Wo_,*q12,*k12,*vt,*y;
    float *ob,*lam;
    GS(xd,g_xd); GS(W,g_W); GS(Wo_,g_Wo);
    GS(q12,g_q12); GS(k12,g_k12); GS(vt,g_vt);
    GS(ob,g_o); GS(y,g_y); GS(lam,g_lam);
    #undef GS

    cudaFuncSetAttribute(gemm_mma, cudaFuncAttributeMaxDynamicSharedMemorySize, GEMM_SMEM);
    cudaFuncSetAttribute(flash_attn, cudaFuncAttributeMaxDynamicSharedMemorySize, FLASH_SMEM);

    // 1. fused prologue: downsample + weight converts + lambda (one launch)
    dim3 gpr(2048, 6);
    prologue_kernel<<<gpr, 256>>>((const float4*)x,
        (const float4*)Wq, (const float4*)Wk, (const float4*)Wv, (const float4*)Wo,
        (ushort4*)xd, (ushort4*)W, (ushort4*)Wo_, lq1, lk1, lq2, lk2, lam);

    // 2. QKV projections with fused normrope (z<2) / v-transpose (z=2) epilogues
    dim3 gqkv(NC/128, (NB*NR)/128, 3);
    gemm_mma<<<gqkv, 256, GEMM_SMEM>>>(xd, W, nullptr, NB*NR, NC, NC,
        0, (long long)NC*NC, 0, 1.f, 3, qw, kw);

    // 3. fused attention (single wave: 128 CTAs x 512 thr) -> g_o
    dim3 gfa(1, NR/256, 2*NB*NH);
    flash_attn<<<gfa, 512, FLASH_SMEM>>>(q12, k12, vt, ob);

    // 4. combine (O1 - lam*O2) + head rmsnorm -> y fp16
    combine_headnorm<<<(32*NR*32 + 255)/256, 256>>>(ob, lam, hw, y);

    // 5. Wo projection + fused silu -> lowrank_out
    dim3 gwo(NC/128, (NB*NR)/128, 1);
    gemm_mma<<<gwo, 256, GEMM_SMEM>>>(y, Wo_, lowrank, NB*NR, NC, NC,
        0, 0, 0, 1.f, 1, nullptr, nullptr);

    // 6. upsample -> full_out
    upsample_kernel<<<(NB*NL*NC/8 + 255)/256, 256>>>((const float4*)lowrank, (float4*)full_out);
}